// round 1
// baseline (speedup 1.0000x reference)
#include <cuda_runtime.h>
#include <math.h>

// Problem constants
#define B_  32
#define T_  2048
#define H_  1024
#define NROWS (B_ * T_)        // 65536
#define NCTILE 16              // H_ / BN

#define BM 64
#define BN 64
#define BK 32

// Scratch (allocation-free rule: __device__ globals)
__device__ float g_partials[NROWS * NCTILE];      // per (row, col-tile) logit partials, 4MB
__device__ float g_ctxPartial[B_ * 4 * H_];       // context partials over 4 T-chunks

// -------------------------------------------------------------------------
// Kernel A: fused GEMM + tanh + dot-with-c, producing logit partials.
// score[r,k] = tanh(sum_h gru[r,h]*W[h,k]);  partial[r, ct] = sum_{k in tile} score*c[k]
// grid: (x = colTile 16, y = rowTile 1024), block 256 (16x16), 4x4 microtile.
// -------------------------------------------------------------------------
__global__ __launch_bounds__(256) void gemm_logits_kernel(
    const float* __restrict__ gru,   // [NROWS, H]
    const float* __restrict__ W,     // [H, H]
    const float* __restrict__ cvec,  // [H]
    float* __restrict__ partials)    // [NROWS, NCTILE]
{
    __shared__ float As[BM][BK + 1];   // [m][k] padded -> conflict-free scalar reads
    __shared__ float Bs[BK][BN];       // [k][n], float4 reads
    __shared__ float cs[BN];
    __shared__ float red[BM][17];

    const int tid = threadIdx.x;
    const int tx  = tid & 15;          // n group
    const int ty  = tid >> 4;          // m group
    const int colBase = blockIdx.x * BN;
    const int rowBase = blockIdx.y * BM;

    if (tid < BN) cs[tid] = cvec[colBase + tid];

    float acc[4][4];
#pragma unroll
    for (int i = 0; i < 4; i++)
#pragma unroll
        for (int j = 0; j < 4; j++) acc[i][j] = 0.f;

    const int aj = tid & 31;   // k within chunk
    const int ai = tid >> 5;   // row 0..7
    const int bn = tid & 63;   // n
    const int bj = tid >> 6;   // k 0..3

    for (int kk = 0; kk < H_; kk += BK) {
#pragma unroll
        for (int p = 0; p < 8; p++)
            As[ai + p * 8][aj] = gru[(size_t)(rowBase + ai + p * 8) * H_ + kk + aj];
#pragma unroll
        for (int p = 0; p < 8; p++)
            Bs[bj + p * 4][bn] = W[(size_t)(kk + bj + p * 4) * H_ + colBase + bn];
        __syncthreads();

#pragma unroll
        for (int k = 0; k < BK; k++) {
            const float a0 = As[ty * 4 + 0][k];
            const float a1 = As[ty * 4 + 1][k];
            const float a2 = As[ty * 4 + 2][k];
            const float a3 = As[ty * 4 + 3][k];
            const float4 b = *(const float4*)&Bs[k][tx * 4];
            acc[0][0] += a0 * b.x; acc[0][1] += a0 * b.y; acc[0][2] += a0 * b.z; acc[0][3] += a0 * b.w;
            acc[1][0] += a1 * b.x; acc[1][1] += a1 * b.y; acc[1][2] += a1 * b.z; acc[1][3] += a1 * b.w;
            acc[2][0] += a2 * b.x; acc[2][1] += a2 * b.y; acc[2][2] += a2 * b.z; acc[2][3] += a2 * b.w;
            acc[3][0] += a3 * b.x; acc[3][1] += a3 * b.y; acc[3][2] += a3 * b.z; acc[3][3] += a3 * b.w;
        }
        __syncthreads();
    }

    // Epilogue: tanh, multiply by c, reduce over the 64 columns of this tile.
    const float4 cv = *(const float4*)&cs[tx * 4];
#pragma unroll
    for (int i = 0; i < 4; i++) {
        float s = tanhf(acc[i][0]) * cv.x + tanhf(acc[i][1]) * cv.y +
                  tanhf(acc[i][2]) * cv.z + tanhf(acc[i][3]) * cv.w;
        red[ty * 4 + i][tx] = s;
    }
    __syncthreads();
    if (tid < BM) {
        float s = 0.f;
#pragma unroll
        for (int q = 0; q < 16; q++) s += red[tid][q];
        partials[(size_t)(rowBase + tid) * NCTILE + blockIdx.x] = s;
    }
}

// -------------------------------------------------------------------------
// Kernel C: reduce partials -> logits, softmax over T per batch, write attn.
// grid 32, block 1024.
// -------------------------------------------------------------------------
__global__ __launch_bounds__(1024) void softmax_kernel(
    const float* __restrict__ partials,
    float* __restrict__ out)           // attn goes to out[B*H + b*T + t]
{
    __shared__ float lg[T_];
    __shared__ float redv[32];
    __shared__ float sBcast;

    const int b = blockIdx.x;
    const int tid = threadIdx.x;

    for (int t = tid; t < T_; t += 1024) {
        const float* p = &partials[(size_t)(b * T_ + t) * NCTILE];
        float s = 0.f;
#pragma unroll
        for (int q = 0; q < NCTILE; q++) s += p[q];
        lg[t] = s;
    }
    __syncthreads();

    // block max
    float m = fmaxf(lg[tid], lg[tid + 1024]);
#pragma unroll
    for (int o = 16; o > 0; o >>= 1) m = fmaxf(m, __shfl_xor_sync(0xffffffffu, m, o));
    if ((tid & 31) == 0) redv[tid >> 5] = m;
    __syncthreads();
    if (tid < 32) {
        float v = redv[tid];
#pragma unroll
        for (int o = 16; o > 0; o >>= 1) v = fmaxf(v, __shfl_xor_sync(0xffffffffu, v, o));
        if (tid == 0) sBcast = v;
    }
    __syncthreads();
    const float M = sBcast;

    const float e0 = expf(lg[tid] - M);
    const float e1 = expf(lg[tid + 1024] - M);
    float z = e0 + e1;
#pragma unroll
    for (int o = 16; o > 0; o >>= 1) z += __shfl_xor_sync(0xffffffffu, z, o);
    if ((tid & 31) == 0) redv[tid >> 5] = z;
    __syncthreads();
    if (tid < 32) {
        float v = redv[tid];
#pragma unroll
        for (int o = 16; o > 0; o >>= 1) v += __shfl_xor_sync(0xffffffffu, v, o);
        if (tid == 0) sBcast = v;
    }
    __syncthreads();
    const float invZ = 1.0f / sBcast;

    float* attn = out + (size_t)B_ * H_ + (size_t)b * T_;
    attn[tid]        = e0 * invZ;
    attn[tid + 1024] = e1 * invZ;
}

// -------------------------------------------------------------------------
// Kernel D1: context partials over T-chunks of 512.
// grid (hc=8, tc=4, b=32), block 128. Each thread owns one h.
// -------------------------------------------------------------------------
__global__ __launch_bounds__(128) void ctx_partial_kernel(
    const float* __restrict__ gru,
    const float* __restrict__ out,      // reads attn from out
    float* __restrict__ ctxp)
{
    __shared__ float at[512];
    const int hc = blockIdx.x, tc = blockIdx.y, b = blockIdx.z;
    const int h  = hc * 128 + threadIdx.x;

    const float* attn = out + (size_t)B_ * H_ + (size_t)b * T_ + tc * 512;
    for (int i = threadIdx.x; i < 512; i += 128) at[i] = attn[i];
    __syncthreads();

    const float* g = gru + ((size_t)b * T_ + tc * 512) * H_ + h;
    float acc = 0.f;
#pragma unroll 8
    for (int t = 0; t < 512; t++) acc += at[t] * g[(size_t)t * H_];

    ctxp[((b * 4 + tc) * H_) + h] = acc;
}

// -------------------------------------------------------------------------
// Kernel D2: reduce 4 T-chunk partials -> context, write to out front.
// grid 32, block 256.
// -------------------------------------------------------------------------
__global__ __launch_bounds__(256) void ctx_reduce_kernel(
    const float* __restrict__ ctxp,
    float* __restrict__ out)
{
    const int b = blockIdx.x;
    for (int h = threadIdx.x; h < H_; h += 256) {
        float s = ctxp[(b * 4 + 0) * H_ + h] + ctxp[(b * 4 + 1) * H_ + h] +
                  ctxp[(b * 4 + 2) * H_ + h] + ctxp[(b * 4 + 3) * H_ + h];
        out[(size_t)b * H_ + h] = s;
    }
}

extern "C" void kernel_launch(void* const* d_in, const int* in_sizes, int n_in,
                              void* d_out, int out_size) {
    const float* gru  = (const float*)d_in[0];   // [32,2048,1024]
    const float* W    = (const float*)d_in[1];   // [1024,1024]
    const float* cvec = (const float*)d_in[2];   // [1024]
    float* out = (float*)d_out;                   // context [32,1024] then attn [32,2048]

    float* partials = nullptr;
    float* ctxp     = nullptr;
    cudaGetSymbolAddress((void**)&partials, g_partials);
    cudaGetSymbolAddress((void**)&ctxp, g_ctxPartial);

    dim3 gA(NCTILE, NROWS / BM);   // col-tile fastest -> gru tile L2 reuse
    gemm_logits_kernel<<<gA, 256>>>(gru, W, cvec, partials);

    softmax_kernel<<<B_, 1024>>>(partials, out);

    dim3 gD(H_ / 128, 4, B_);
    ctx_partial_kernel<<<gD, 128>>>(gru, out, ctxp);

    ctx_reduce_kernel<<<B_, 256>>>(ctxp, out);
}

// round 3
// speedup vs baseline: 3.9035x; 3.9035x over previous
#include <cuda_runtime.h>
#include <math.h>
#include <stdint.h>

// ---------------- problem constants ----------------
#define B_  32
#define T_  2048
#define H_  1024
#define NROWS (B_ * T_)          // 65536

// GEMM tiling
#define BM 256
#define BN 128
#define BKC 32
#define NCTILE (H_ / BN)         // 8
#define CHUNKS (H_ / BKC)        // 32

// dynamic smem: A0[32K] A1[32K] B0[16K] B1[16K]
#define OFF_A0 0
#define OFF_A1 32768
#define OFF_B0 65536
#define OFF_B1 81920
#define DSMEM_BYTES 98304

// ---------------- device scratch ----------------
__device__ float g_Wt[H_ * H_];                 // W^T, tf32-rounded
__device__ float g_partials[NROWS * NCTILE];
__device__ float g_ctxPartial[B_ * 4 * H_];

// ---------------- PTX helpers (baseline ISA only — no sm_103a features) ----
__device__ __forceinline__ uint32_t smem_u32(const void* p) {
    uint32_t a;
    asm("{ .reg .u64 t; cvta.to.shared.u64 t, %1; cvt.u32.u64 %0, t; }" : "=r"(a) : "l"(p));
    return a;
}
__device__ __forceinline__ float to_tf32(float x) {
    uint32_t u;
    asm("cvt.rna.tf32.f32 %0, %1;" : "=r"(u) : "f"(x));
    return __uint_as_float(u);
}
__device__ __forceinline__ void ldsm4(uint32_t& r0, uint32_t& r1, uint32_t& r2,
                                      uint32_t& r3, uint32_t addr) {
    asm volatile("ldmatrix.sync.aligned.m8n8.x4.shared.b16 {%0,%1,%2,%3}, [%4];"
                 : "=r"(r0), "=r"(r1), "=r"(r2), "=r"(r3) : "r"(addr));
}
__device__ __forceinline__ void mma_tf32(float* d, const uint32_t* a,
                                         uint32_t b0, uint32_t b1) {
    asm volatile("mma.sync.aligned.m16n8k8.row.col.f32.tf32.tf32.f32 "
                 "{%0,%1,%2,%3}, {%4,%5,%6,%7}, {%8,%9}, {%0,%1,%2,%3};"
                 : "+f"(d[0]), "+f"(d[1]), "+f"(d[2]), "+f"(d[3])
                 : "r"(a[0]), "r"(a[1]), "r"(a[2]), "r"(a[3]), "r"(b0), "r"(b1));
}
#define CP_ASYNC16(dst, src) \
    asm volatile("cp.async.cg.shared.global [%0], [%1], 16;" :: "r"(dst), "l"(src))
#define CP_COMMIT() asm volatile("cp.async.commit_group;" ::: "memory")
#define CP_WAIT0()  asm volatile("cp.async.wait_group 0;" ::: "memory")

// ---------------- kernel 0: transpose + tf32-round W ----------------
__global__ __launch_bounds__(256) void transpose_w_kernel(const float* __restrict__ W,
                                                          float* __restrict__ Wt) {
    __shared__ float t[32][33];
    const int tx = threadIdx.x, ty = threadIdx.y;        // (32, 8)
    const int bx = blockIdx.x * 32, by = blockIdx.y * 32;
#pragma unroll
    for (int i = 0; i < 32; i += 8)
        t[ty + i][tx] = W[(size_t)(by + ty + i) * H_ + bx + tx];
    __syncthreads();
#pragma unroll
    for (int i = 0; i < 32; i += 8)
        Wt[(size_t)(bx + ty + i) * H_ + by + tx] = to_tf32(t[tx][ty + i]);
}

// ---------------- kernel A: tf32 mma.sync GEMM + tanh·c partial reduce -----
// grid (NCTILE=8, NROWS/BM=256), block 256 (8 warps, warp tile 64x64)
__global__ __launch_bounds__(256, 1) void gemm_mma_kernel(
    const float* __restrict__ gru,   // [NROWS, H]
    const float* __restrict__ Wt,    // [H, H] = W^T, tf32-rounded
    const float* __restrict__ cvec,  // [H]
    float* __restrict__ partials)    // [NROWS, NCTILE]
{
    extern __shared__ char dsm[];
    __shared__ float cs[BN];
    __shared__ float red[BM][2];

    const uint32_t sbase = smem_u32(dsm);
    const int tid  = threadIdx.x;
    const int lane = tid & 31;
    const int wid  = tid >> 5;
    const int warpM = wid & 3;       // 4 -> rows
    const int warpN = wid >> 2;      // 2 -> cols
    const int colBase = blockIdx.x * BN;
    const int rowBase = blockIdx.y * BM;

    if (tid < BN) cs[tid] = cvec[colBase + tid];

    // loader geometry: seg (16B unit) fixed per thread, rows strided by 32
    const int ldRow = tid >> 3;               // 0..31
    const int ldSeg = tid & 7;                // 0..7
    const int sseg  = ldSeg ^ (ldRow & 7);    // SW128-swizzled seg (constant!)
    const uint32_t aDstBase = (uint32_t)(ldRow * 128 + sseg * 16);
    const uint32_t bDstBase = aDstBase;

    const float* Ag = gru + (size_t)(rowBase + ldRow) * H_ + ldSeg * 4;
    const float* Bg = Wt  + (size_t)(colBase + ldRow) * H_ + ldSeg * 4;

    float acc[4][8][4];
#pragma unroll
    for (int i = 0; i < 4; i++)
#pragma unroll
        for (int j = 0; j < 8; j++)
#pragma unroll
            for (int k = 0; k < 4; k++) acc[i][j][k] = 0.f;

    const uint32_t offA[2] = {OFF_A0, OFF_A1};
    const uint32_t offB[2] = {OFF_B0, OFF_B1};

    // ---- preload chunk 0 ----
    {
#pragma unroll
        for (int p = 0; p < 4; p++)
            CP_ASYNC16(sbase + OFF_B0 + bDstBase + p * 32 * 128,
                       Bg + (size_t)(p * 32) * H_);
        CP_COMMIT();
        float4 v[8];
#pragma unroll
        for (int p = 0; p < 8; p++)
            v[p] = *(const float4*)(Ag + (size_t)(p * 32) * H_);
#pragma unroll
        for (int p = 0; p < 8; p++) {
            float4 w;
            w.x = to_tf32(v[p].x); w.y = to_tf32(v[p].y);
            w.z = to_tf32(v[p].z); w.w = to_tf32(v[p].w);
            *(float4*)(dsm + OFF_A0 + aDstBase + p * 32 * 128) = w;
        }
        CP_WAIT0();
    }
    __syncthreads();

    int buf = 0;
    for (int ck = 0; ck < CHUNKS; ck++) {
        float4 v[8];
        const bool more = (ck + 1 < CHUNKS);
        if (more) {
            const int kk = (ck + 1) * BKC;
#pragma unroll
            for (int p = 0; p < 4; p++)
                CP_ASYNC16(sbase + offB[buf ^ 1] + bDstBase + p * 32 * 128,
                           Bg + kk + (size_t)(p * 32) * H_);
            CP_COMMIT();
#pragma unroll
            for (int p = 0; p < 8; p++)
                v[p] = *(const float4*)(Ag + kk + (size_t)(p * 32) * H_);
        }

        // ---- compute on buf ----
        const uint32_t aBuf = sbase + offA[buf];
        const uint32_t bBuf = sbase + offB[buf];
#pragma unroll
        for (int s = 0; s < 4; s++) {
            uint32_t afr[4][4];
#pragma unroll
            for (int mt = 0; mt < 4; mt++) {
                const int r = warpM * 64 + mt * 16 + (lane & 15);
                const int seg16 = 2 * s + (lane >> 4);
                ldsm4(afr[mt][0], afr[mt][1], afr[mt][2], afr[mt][3],
                      aBuf + r * 128 + ((seg16 ^ (r & 7)) << 4));
            }
            uint32_t bfr[4][4];
#pragma unroll
            for (int q = 0; q < 4; q++) {
                const int rn = warpN * 64 + q * 16 + ((lane >> 4) << 3) + (lane & 7);
                const int seg16 = 2 * s + ((lane >> 3) & 1);
                ldsm4(bfr[q][0], bfr[q][1], bfr[q][2], bfr[q][3],
                      bBuf + rn * 128 + ((seg16 ^ (rn & 7)) << 4));
            }
#pragma unroll
            for (int mt = 0; mt < 4; mt++)
#pragma unroll
                for (int nt = 0; nt < 8; nt++) {
                    const int q = nt >> 1;
                    if ((nt & 1) == 0)
                        mma_tf32(acc[mt][nt], afr[mt], bfr[q][0], bfr[q][1]);
                    else
                        mma_tf32(acc[mt][nt], afr[mt], bfr[q][2], bfr[q][3]);
                }
        }

        if (more) {
#pragma unroll
            for (int p = 0; p < 8; p++) {
                float4 w;
                w.x = to_tf32(v[p].x); w.y = to_tf32(v[p].y);
                w.z = to_tf32(v[p].z); w.w = to_tf32(v[p].w);
                *(float4*)(dsm + offA[buf ^ 1] + aDstBase + p * 32 * 128) = w;
            }
            CP_WAIT0();
        }
        __syncthreads();
        buf ^= 1;
    }

    // ---- epilogue: sum_n tanh(D) * c over this CTA's 128 cols ----
#pragma unroll
    for (int mt = 0; mt < 4; mt++) {
        float slo = 0.f, shi = 0.f;
#pragma unroll
        for (int nt = 0; nt < 8; nt++) {
            const int n = warpN * 64 + nt * 8 + (lane & 3) * 2;
            const float c0 = cs[n], c1 = cs[n + 1];
            slo += tanhf(acc[mt][nt][0]) * c0 + tanhf(acc[mt][nt][1]) * c1;
            shi += tanhf(acc[mt][nt][2]) * c0 + tanhf(acc[mt][nt][3]) * c1;
        }
        slo += __shfl_xor_sync(0xffffffffu, slo, 1);
        slo += __shfl_xor_sync(0xffffffffu, slo, 2);
        shi += __shfl_xor_sync(0xffffffffu, shi, 1);
        shi += __shfl_xor_sync(0xffffffffu, shi, 2);
        if ((lane & 3) == 0) {
            const int r0 = warpM * 64 + mt * 16 + (lane >> 2);
            red[r0][warpN]     = slo;
            red[r0 + 8][warpN] = shi;
        }
    }
    __syncthreads();
    partials[(size_t)(rowBase + tid) * NCTILE + blockIdx.x] = red[tid][0] + red[tid][1];
}

// ---------------- kernel C: logits reduce + softmax over T ----------------
__global__ __launch_bounds__(1024) void softmax_kernel(
    const float* __restrict__ partials, float* __restrict__ out)
{
    __shared__ float lg[T_];
    __shared__ float redv[32];
    __shared__ float sBcast;
    const int b = blockIdx.x, tid = threadIdx.x;

    for (int t = tid; t < T_; t += 1024) {
        const float* p = &partials[(size_t)(b * T_ + t) * NCTILE];
        float s = 0.f;
#pragma unroll
        for (int q = 0; q < NCTILE; q++) s += p[q];
        lg[t] = s;
    }
    __syncthreads();

    float m = fmaxf(lg[tid], lg[tid + 1024]);
#pragma unroll
    for (int o = 16; o > 0; o >>= 1) m = fmaxf(m, __shfl_xor_sync(0xffffffffu, m, o));
    if ((tid & 31) == 0) redv[tid >> 5] = m;
    __syncthreads();
    if (tid < 32) {
        float v = redv[tid];
#pragma unroll
        for (int o = 16; o > 0; o >>= 1) v = fmaxf(v, __shfl_xor_sync(0xffffffffu, v, o));
        if (tid == 0) sBcast = v;
    }
    __syncthreads();
    const float M = sBcast;

    const float e0 = expf(lg[tid] - M);
    const float e1 = expf(lg[tid + 1024] - M);
    float z = e0 + e1;
#pragma unroll
    for (int o = 16; o > 0; o >>= 1) z += __shfl_xor_sync(0xffffffffu, z, o);
    if ((tid & 31) == 0) redv[tid >> 5] = z;
    __syncthreads();
    if (tid < 32) {
        float v = redv[tid];
#pragma unroll
        for (int o = 16; o > 0; o >>= 1) v += __shfl_xor_sync(0xffffffffu, v, o);
        if (tid == 0) sBcast = v;
    }
    __syncthreads();
    const float invZ = 1.0f / sBcast;

    float* attn = out + (size_t)B_ * H_ + (size_t)b * T_;
    attn[tid]        = e0 * invZ;
    attn[tid + 1024] = e1 * invZ;
}

// ---------------- kernel D1: context partials over 4 T-chunks ----------------
__global__ __launch_bounds__(128) void ctx_partial_kernel(
    const float* __restrict__ gru, const float* __restrict__ out,
    float* __restrict__ ctxp)
{
    __shared__ float at[512];
    const int hc = blockIdx.x, tc = blockIdx.y, b = blockIdx.z;
    const int h = hc * 128 + threadIdx.x;

    const float* attn = out + (size_t)B_ * H_ + (size_t)b * T_ + tc * 512;
    for (int i = threadIdx.x; i < 512; i += 128) at[i] = attn[i];
    __syncthreads();

    const float* g = gru + ((size_t)b * T_ + tc * 512) * H_ + h;
    float acc = 0.f;
#pragma unroll 8
    for (int t = 0; t < 512; t++) acc += at[t] * g[(size_t)t * H_];

    ctxp[((b * 4 + tc) * H_) + h] = acc;
}

// ---------------- kernel D2: reduce context partials ----------------
__global__ __launch_bounds__(256) void ctx_reduce_kernel(
    const float* __restrict__ ctxp, float* __restrict__ out)
{
    const int b = blockIdx.x;
    for (int h = threadIdx.x; h < H_; h += 256) {
        float s = ctxp[(b * 4 + 0) * H_ + h] + ctxp[(b * 4 + 1) * H_ + h] +
                  ctxp[(b * 4 + 2) * H_ + h] + ctxp[(b * 4 + 3) * H_ + h];
        out[(size_t)b * H_ + h] = s;
    }
}

// ---------------- launch ----------------
extern "C" void kernel_launch(void* const* d_in, const int* in_sizes, int n_in,
                              void* d_out, int out_size) {
    const float* gru  = (const float*)d_in[0];
    const float* W    = (const float*)d_in[1];
    const float* cvec = (const float*)d_in[2];
    float* out = (float*)d_out;

    float *Wt = nullptr, *partials = nullptr, *ctxp = nullptr;
    cudaGetSymbolAddress((void**)&Wt, g_Wt);
    cudaGetSymbolAddress((void**)&partials, g_partials);
    cudaGetSymbolAddress((void**)&ctxp, g_ctxPartial);

    cudaFuncSetAttribute(gemm_mma_kernel,
                         cudaFuncAttributeMaxDynamicSharedMemorySize, DSMEM_BYTES);

    transpose_w_kernel<<<dim3(32, 32), dim3(32, 8)>>>(W, Wt);

    gemm_mma_kernel<<<dim3(NCTILE, NROWS / BM), 256, DSMEM_BYTES>>>(gru, Wt, cvec, partials);

    softmax_kernel<<<B_, 1024>>>(partials, out);

    ctx_partial_kernel<<<dim3(H_ / 128, 4, B_), 128>>>(gru, out, ctxp);

    ctx_reduce_kernel<<<B_, 256>>>(ctxp, out);
}

// round 4
// speedup vs baseline: 4.4828x; 1.1484x over previous
#include <cuda_runtime.h>
#include <math.h>
#include <stdint.h>

// ---------------- problem constants ----------------
#define B_  32
#define T_  2048
#define H_  1024
#define NROWS (B_ * T_)          // 65536

// GEMM tiling
#define BM 256
#define BN 128
#define BKC 32
#define NCTILE (H_ / BN)         // 8
#define CHUNKS (H_ / BKC)        // 32

// dynamic smem: A0[32K] A1[32K] B0[16K] B1[16K]
#define OFF_A0 0
#define OFF_A1 32768
#define OFF_B0 65536
#define OFF_B1 81920
#define DSMEM_BYTES 98304

// ctx pass tiling
#define CTC 8                    // T chunks
#define CTS (T_ / CTC)           // 256

// ---------------- device scratch ----------------
__device__ float g_Wt[H_ * H_];                 // W^T, tf32-rounded
__device__ float g_partials[NROWS * NCTILE];
__device__ float g_ctxPartial[B_ * CTC * H_];
__device__ float g_dummy[32];

// ---------------- PTX helpers (baseline ISA only) ----------------
__device__ __forceinline__ uint32_t smem_u32(const void* p) {
    uint32_t a;
    asm("{ .reg .u64 t; cvta.to.shared.u64 t, %1; cvt.u32.u64 %0, t; }" : "=r"(a) : "l"(p));
    return a;
}
__device__ __forceinline__ float to_tf32(float x) {
    uint32_t u;
    asm("cvt.rna.tf32.f32 %0, %1;" : "=r"(u) : "f"(x));
    return __uint_as_float(u);
}
__device__ __forceinline__ void ldsm4(uint32_t& r0, uint32_t& r1, uint32_t& r2,
                                      uint32_t& r3, uint32_t addr) {
    asm volatile("ldmatrix.sync.aligned.m8n8.x4.shared.b16 {%0,%1,%2,%3}, [%4];"
                 : "=r"(r0), "=r"(r1), "=r"(r2), "=r"(r3) : "r"(addr));
}
__device__ __forceinline__ void mma_tf32(float* d, const uint32_t* a,
                                         uint32_t b0, uint32_t b1) {
    asm volatile("mma.sync.aligned.m16n8k8.row.col.f32.tf32.tf32.f32 "
                 "{%0,%1,%2,%3}, {%4,%5,%6,%7}, {%8,%9}, {%0,%1,%2,%3};"
                 : "+f"(d[0]), "+f"(d[1]), "+f"(d[2]), "+f"(d[3])
                 : "r"(a[0]), "r"(a[1]), "r"(a[2]), "r"(a[3]), "r"(b0), "r"(b1));
}
#define CP_ASYNC16(dst, src) \
    asm volatile("cp.async.cg.shared.global [%0], [%1], 16;" :: "r"(dst), "l"(src))
#define CP_COMMIT() asm volatile("cp.async.commit_group;" ::: "memory")
#define CP_WAIT0()  asm volatile("cp.async.wait_group 0;" ::: "memory")

// ---------------- kernel 0: transpose + tf32-round W ----------------
__global__ __launch_bounds__(256) void transpose_w_kernel(const float* __restrict__ W,
                                                          float* __restrict__ Wt) {
    __shared__ float t[32][33];
    const int tx = threadIdx.x, ty = threadIdx.y;        // (32, 8)
    const int bx = blockIdx.x * 32, by = blockIdx.y * 32;
#pragma unroll
    for (int i = 0; i < 32; i += 8)
        t[ty + i][tx] = W[(size_t)(by + ty + i) * H_ + bx + tx];
    __syncthreads();
#pragma unroll
    for (int i = 0; i < 32; i += 8)
        Wt[(size_t)(bx + ty + i) * H_ + by + tx] = to_tf32(t[tx][ty + i]);
}

// ---------------- tiny dummies (steer ncu onto the GEMM at in-call idx 3) --
__global__ void dummy_kernel_a(float* d) { if (threadIdx.x == 0) d[0] = 1.0f; }
__global__ void dummy_kernel_b(float* d) { if (threadIdx.x == 0) d[1] = 2.0f; }

// ---------------- kernel A: tf32 mma.sync GEMM + tanh·c partial reduce -----
// grid (NCTILE=8, NROWS/BM=256), block 256 (8 warps, warp tile 64x64)
// A streamed raw fp32 via cp.async (HMMA truncates to tf32); B pre-rounded.
__global__ __launch_bounds__(256, 1) void gemm_mma_kernel(
    const float* __restrict__ gru,   // [NROWS, H]
    const float* __restrict__ Wt,    // [H, H] = W^T, tf32-rounded
    const float* __restrict__ cvec,  // [H]
    float* __restrict__ partials)    // [NROWS, NCTILE]
{
    extern __shared__ char dsm[];
    __shared__ float cs[BN];
    __shared__ float red[BM][2];

    const uint32_t sbase = smem_u32(dsm);
    const int tid  = threadIdx.x;
    const int lane = tid & 31;
    const int wid  = tid >> 5;
    const int warpM = wid & 3;       // 4 -> rows
    const int warpN = wid >> 2;      // 2 -> cols
    const int colBase = blockIdx.x * BN;
    const int rowBase = blockIdx.y * BM;

    if (tid < BN) cs[tid] = cvec[colBase + tid];

    // loader geometry: seg (16B unit) fixed per thread, rows strided by 32
    const int ldRow = tid >> 3;               // 0..31
    const int ldSeg = tid & 7;                // 0..7
    const int sseg  = ldSeg ^ (ldRow & 7);    // SW128-swizzled seg (constant)
    const uint32_t dstBase = (uint32_t)(ldRow * 128 + sseg * 16);

    const float* Ag = gru + (size_t)(rowBase + ldRow) * H_ + ldSeg * 4;
    const float* Bg = Wt  + (size_t)(colBase + ldRow) * H_ + ldSeg * 4;

    float acc[4][8][4];
#pragma unroll
    for (int i = 0; i < 4; i++)
#pragma unroll
        for (int j = 0; j < 8; j++)
#pragma unroll
            for (int k = 0; k < 4; k++) acc[i][j][k] = 0.f;

    const uint32_t offA[2] = {OFF_A0, OFF_A1};
    const uint32_t offB[2] = {OFF_B0, OFF_B1};

    // ---- preload chunk 0 ----
#pragma unroll
    for (int p = 0; p < 8; p++)
        CP_ASYNC16(sbase + OFF_A0 + dstBase + p * 4096, Ag + (size_t)(p * 32) * H_);
#pragma unroll
    for (int p = 0; p < 4; p++)
        CP_ASYNC16(sbase + OFF_B0 + dstBase + p * 4096, Bg + (size_t)(p * 32) * H_);
    CP_COMMIT();
    CP_WAIT0();
    __syncthreads();

    int buf = 0;
    for (int ck = 0; ck < CHUNKS; ck++) {
        const bool more = (ck + 1 < CHUNKS);
        if (more) {
            const int kk = (ck + 1) * BKC;
#pragma unroll
            for (int p = 0; p < 8; p++)
                CP_ASYNC16(sbase + offA[buf ^ 1] + dstBase + p * 4096,
                           Ag + kk + (size_t)(p * 32) * H_);
#pragma unroll
            for (int p = 0; p < 4; p++)
                CP_ASYNC16(sbase + offB[buf ^ 1] + dstBase + p * 4096,
                           Bg + kk + (size_t)(p * 32) * H_);
            CP_COMMIT();
        }

        // ---- compute on buf ----
        const uint32_t aBuf = sbase + offA[buf];
        const uint32_t bBuf = sbase + offB[buf];
#pragma unroll
        for (int s = 0; s < 4; s++) {
            uint32_t afr[4][4];
#pragma unroll
            for (int mt = 0; mt < 4; mt++) {
                const int r = warpM * 64 + mt * 16 + (lane & 15);
                const int seg16 = 2 * s + (lane >> 4);
                ldsm4(afr[mt][0], afr[mt][1], afr[mt][2], afr[mt][3],
                      aBuf + r * 128 + ((seg16 ^ (r & 7)) << 4));
            }
            uint32_t bfr[4][4];
#pragma unroll
            for (int q = 0; q < 4; q++) {
                const int rn = warpN * 64 + q * 16 + ((lane >> 4) << 3) + (lane & 7);
                const int seg16 = 2 * s + ((lane >> 3) & 1);
                ldsm4(bfr[q][0], bfr[q][1], bfr[q][2], bfr[q][3],
                      bBuf + rn * 128 + ((seg16 ^ (rn & 7)) << 4));
            }
#pragma unroll
            for (int mt = 0; mt < 4; mt++)
#pragma unroll
                for (int nt = 0; nt < 8; nt++) {
                    const int q = nt >> 1;
                    if ((nt & 1) == 0)
                        mma_tf32(acc[mt][nt], afr[mt], bfr[q][0], bfr[q][1]);
                    else
                        mma_tf32(acc[mt][nt], afr[mt], bfr[q][2], bfr[q][3]);
                }
        }

        if (more) CP_WAIT0();
        __syncthreads();
        buf ^= 1;
    }

    // ---- epilogue: sum_n tanh(D) * c over this CTA's 128 cols ----
#pragma unroll
    for (int mt = 0; mt < 4; mt++) {
        float slo = 0.f, shi = 0.f;
#pragma unroll
        for (int nt = 0; nt < 8; nt++) {
            const int n = warpN * 64 + nt * 8 + (lane & 3) * 2;
            const float c0 = cs[n], c1 = cs[n + 1];
            slo += tanhf(acc[mt][nt][0]) * c0 + tanhf(acc[mt][nt][1]) * c1;
            shi += tanhf(acc[mt][nt][2]) * c0 + tanhf(acc[mt][nt][3]) * c1;
        }
        slo += __shfl_xor_sync(0xffffffffu, slo, 1);
        slo += __shfl_xor_sync(0xffffffffu, slo, 2);
        shi += __shfl_xor_sync(0xffffffffu, shi, 1);
        shi += __shfl_xor_sync(0xffffffffu, shi, 2);
        if ((lane & 3) == 0) {
            const int r0 = warpM * 64 + mt * 16 + (lane >> 2);
            red[r0][warpN]     = slo;
            red[r0 + 8][warpN] = shi;
        }
    }
    __syncthreads();
    partials[(size_t)(rowBase + tid) * NCTILE + blockIdx.x] = red[tid][0] + red[tid][1];
}

// ---------------- kernel C: logits reduce + softmax over T ----------------
__global__ __launch_bounds__(1024) void softmax_kernel(
    const float* __restrict__ partials, float* __restrict__ out)
{
    __shared__ float lg[T_];
    __shared__ float redv[32];
    __shared__ float sBcast;
    const int b = blockIdx.x, tid = threadIdx.x;

    for (int t = tid; t < T_; t += 1024) {
        const float* p = &partials[(size_t)(b * T_ + t) * NCTILE];
        float s = 0.f;
#pragma unroll
        for (int q = 0; q < NCTILE; q++) s += p[q];
        lg[t] = s;
    }
    __syncthreads();

    float m = fmaxf(lg[tid], lg[tid + 1024]);
#pragma unroll
    for (int o = 16; o > 0; o >>= 1) m = fmaxf(m, __shfl_xor_sync(0xffffffffu, m, o));
    if ((tid & 31) == 0) redv[tid >> 5] = m;
    __syncthreads();
    if (tid < 32) {
        float v = redv[tid];
#pragma unroll
        for (int o = 16; o > 0; o >>= 1) v = fmaxf(v, __shfl_xor_sync(0xffffffffu, v, o));
        if (tid == 0) sBcast = v;
    }
    __syncthreads();
    const float M = sBcast;

    const float e0 = expf(lg[tid] - M);
    const float e1 = expf(lg[tid + 1024] - M);
    float z = e0 + e1;
#pragma unroll
    for (int o = 16; o > 0; o >>= 1) z += __shfl_xor_sync(0xffffffffu, z, o);
    if ((tid & 31) == 0) redv[tid >> 5] = z;
    __syncthreads();
    if (tid < 32) {
        float v = redv[tid];
#pragma unroll
        for (int o = 16; o > 0; o >>= 1) v += __shfl_xor_sync(0xffffffffu, v, o);
        if (tid == 0) sBcast = v;
    }
    __syncthreads();
    const float invZ = 1.0f / sBcast;

    float* attn = out + (size_t)B_ * H_ + (size_t)b * T_;
    attn[tid]        = e0 * invZ;
    attn[tid + 1024] = e1 * invZ;
}

// ---------------- kernel D1: context partials over 8 T-chunks ----------------
// grid (4 hc, CTC tc, B), block 256; thread owns one h
__global__ __launch_bounds__(256) void ctx_partial_kernel(
    const float* __restrict__ gru, const float* __restrict__ out,
    float* __restrict__ ctxp)
{
    __shared__ float at[CTS];
    const int hc = blockIdx.x, tc = blockIdx.y, b = blockIdx.z;
    const int h = hc * 256 + threadIdx.x;

    const float* attn = out + (size_t)B_ * H_ + (size_t)b * T_ + tc * CTS;
    if (threadIdx.x < CTS) at[threadIdx.x] = attn[threadIdx.x];
    __syncthreads();

    const float* g = gru + ((size_t)b * T_ + tc * CTS) * H_ + h;
    float acc = 0.f;
#pragma unroll 8
    for (int t = 0; t < CTS; t++) acc += at[t] * g[(size_t)t * H_];

    ctxp[((b * CTC + tc) * H_) + h] = acc;
}

// ---------------- kernel D2: reduce context partials ----------------
__global__ __launch_bounds__(256) void ctx_reduce_kernel(
    const float* __restrict__ ctxp, float* __restrict__ out)
{
    const int b = blockIdx.x;
    for (int h = threadIdx.x; h < H_; h += 256) {
        float s = 0.f;
#pragma unroll
        for (int q = 0; q < CTC; q++) s += ctxp[(b * CTC + q) * H_ + h];
        out[(size_t)b * H_ + h] = s;
    }
}

// ---------------- launch ----------------
extern "C" void kernel_launch(void* const* d_in, const int* in_sizes, int n_in,
                              void* d_out, int out_size) {
    const float* gru  = (const float*)d_in[0];
    const float* W    = (const float*)d_in[1];
    const float* cvec = (const float*)d_in[2];
    float* out = (float*)d_out;

    float *Wt = nullptr, *partials = nullptr, *ctxp = nullptr, *dmy = nullptr;
    cudaGetSymbolAddress((void**)&Wt, g_Wt);
    cudaGetSymbolAddress((void**)&partials, g_partials);
    cudaGetSymbolAddress((void**)&ctxp, g_ctxPartial);
    cudaGetSymbolAddress((void**)&dmy, g_dummy);

    cudaFuncSetAttribute(gemm_mma_kernel,
                         cudaFuncAttributeMaxDynamicSharedMemorySize, DSMEM_BYTES);

    transpose_w_kernel<<<dim3(32, 32), dim3(32, 8)>>>(W, Wt);      // idx 0
    dummy_kernel_a<<<1, 32>>>(dmy);                                 // idx 1
    dummy_kernel_b<<<1, 32>>>(dmy);                                 // idx 2

    gemm_mma_kernel<<<dim3(NCTILE, NROWS / BM), 256, DSMEM_BYTES>>>(gru, Wt, cvec, partials); // idx 3

    softmax_kernel<<<B_, 1024>>>(partials, out);

    ctx_partial_kernel<<<dim3(4, CTC, B_), 256>>>(gru, out, ctxp);

    ctx_reduce_kernel<<<B_, 256>>>(ctxp, out);
}

// round 5
// speedup vs baseline: 4.5508x; 1.0152x over previous
#include <cuda_runtime.h>
#include <math.h>
#include <stdint.h>

// ---------------- problem constants ----------------
#define B_  32
#define T_  2048
#define H_  1024
#define NROWS (B_ * T_)          // 65536

// GEMM tiling
#define BM 256
#define BN 128
#define BKC 32
#define NCTILE (H_ / BN)         // 8
#define CHUNKS (H_ / BKC)        // 32

// dynamic smem: A0[32K] A1[32K] B0[16K] B1[16K]
#define OFF_A0 0
#define OFF_A1 32768
#define OFF_B0 65536
#define OFF_B1 81920
#define DSMEM_BYTES 98304

// ctx pass tiling
#define CTC 8                    // T chunks
#define CTS (T_ / CTC)           // 256

// ---------------- device scratch ----------------
__device__ float g_Wt[H_ * H_];                 // W^T, tf32-rounded
__device__ float g_partials[NROWS * NCTILE];
__device__ float g_ctxPartial[B_ * CTC * H_];
__device__ float g_dummy[32];

// ---------------- PTX helpers (baseline ISA only) ----------------
__device__ __forceinline__ uint32_t smem_u32(const void* p) {
    uint32_t a;
    asm("{ .reg .u64 t; cvta.to.shared.u64 t, %1; cvt.u32.u64 %0, t; }" : "=r"(a) : "l"(p));
    return a;
}
__device__ __forceinline__ float to_tf32(float x) {
    uint32_t u;
    asm("cvt.rna.tf32.f32 %0, %1;" : "=r"(u) : "f"(x));
    return __uint_as_float(u);
}
__device__ __forceinline__ void ldsm4(uint32_t& r0, uint32_t& r1, uint32_t& r2,
                                      uint32_t& r3, uint32_t addr) {
    asm volatile("ldmatrix.sync.aligned.m8n8.x4.shared.b16 {%0,%1,%2,%3}, [%4];"
                 : "=r"(r0), "=r"(r1), "=r"(r2), "=r"(r3) : "r"(addr));
}
__device__ __forceinline__ void mma_tf32(float* d, const uint32_t* a,
                                         uint32_t b0, uint32_t b1) {
    asm volatile("mma.sync.aligned.m16n8k8.row.col.f32.tf32.tf32.f32 "
                 "{%0,%1,%2,%3}, {%4,%5,%6,%7}, {%8,%9}, {%0,%1,%2,%3};"
                 : "+f"(d[0]), "+f"(d[1]), "+f"(d[2]), "+f"(d[3])
                 : "r"(a[0]), "r"(a[1]), "r"(a[2]), "r"(a[3]), "r"(b0), "r"(b1));
}
#define CP_ASYNC16(dst, src) \
    asm volatile("cp.async.cg.shared.global [%0], [%1], 16;" :: "r"(dst), "l"(src))
#define CP_COMMIT() asm volatile("cp.async.commit_group;" ::: "memory")
#define CP_WAIT0()  asm volatile("cp.async.wait_group 0;" ::: "memory")

// ---------------- kernel 0: transpose + tf32-round W ----------------
__global__ __launch_bounds__(256) void transpose_w_kernel(const float* __restrict__ W,
                                                          float* __restrict__ Wt) {
    __shared__ float t[32][33];
    const int tx = threadIdx.x, ty = threadIdx.y;        // (32, 8)
    const int bx = blockIdx.x * 32, by = blockIdx.y * 32;
#pragma unroll
    for (int i = 0; i < 32; i += 8)
        t[ty + i][tx] = W[(size_t)(by + ty + i) * H_ + bx + tx];
    __syncthreads();
#pragma unroll
    for (int i = 0; i < 32; i += 8)
        Wt[(size_t)(bx + ty + i) * H_ + by + tx] = to_tf32(t[tx][ty + i]);
}

// ---------------- tiny dummies (steer ncu onto the GEMM at in-call idx 3) --
__global__ void dummy_kernel_a(float* d) { if (threadIdx.x == 0) d[0] = 1.0f; }
__global__ void dummy_kernel_b(float* d) { if (threadIdx.x == 0) d[1] = 2.0f; }

// ---------------- kernel A: tf32 mma.sync GEMM + tanh·c partial reduce -----
// grid (NCTILE=8, NROWS/BM=256), block 512 (16 warps: 4x4, warp tile 64x32)
__global__ __launch_bounds__(512, 1) void gemm_mma_kernel(
    const float* __restrict__ gru,   // [NROWS, H]
    const float* __restrict__ Wt,    // [H, H] = W^T, tf32-rounded
    const float* __restrict__ cvec,  // [H]
    float* __restrict__ partials)    // [NROWS, NCTILE]
{
    extern __shared__ char dsm[];
    __shared__ float cs[BN];
    __shared__ float red[BM][4];

    const uint32_t sbase = smem_u32(dsm);
    const int tid  = threadIdx.x;
    const int lane = tid & 31;
    const int wid  = tid >> 5;
    const int warpM = wid & 3;       // 4 -> row groups of 64
    const int warpN = wid >> 2;      // 4 -> col groups of 32
    const int colBase = blockIdx.x * BN;
    const int rowBase = blockIdx.y * BM;

    if (tid < BN) cs[tid] = cvec[colBase + tid];

    // loader geometry: 512 threads, 8 segs/row -> 64 rows per pass
    const int ldRow = tid >> 3;               // 0..63
    const int ldSeg = tid & 7;                // 0..7
    const int sseg  = ldSeg ^ (ldRow & 7);    // SW128-swizzled seg (constant)
    const uint32_t dstBase = (uint32_t)(ldRow * 128 + sseg * 16);

    const float* Ag = gru + (size_t)(rowBase + ldRow) * H_ + ldSeg * 4;
    const float* Bg = Wt  + (size_t)(colBase + ldRow) * H_ + ldSeg * 4;

    float acc[4][4][4];
#pragma unroll
    for (int i = 0; i < 4; i++)
#pragma unroll
        for (int j = 0; j < 4; j++)
#pragma unroll
            for (int k = 0; k < 4; k++) acc[i][j][k] = 0.f;

    const uint32_t offA[2] = {OFF_A0, OFF_A1};
    const uint32_t offB[2] = {OFF_B0, OFF_B1};

    // ---- preload chunk 0 ----
#pragma unroll
    for (int p = 0; p < 4; p++)           // A: 256 rows
        CP_ASYNC16(sbase + OFF_A0 + dstBase + p * 8192, Ag + (size_t)(p * 64) * H_);
#pragma unroll
    for (int p = 0; p < 2; p++)           // B: 128 rows
        CP_ASYNC16(sbase + OFF_B0 + dstBase + p * 8192, Bg + (size_t)(p * 64) * H_);
    CP_COMMIT();
    CP_WAIT0();
    __syncthreads();

    int buf = 0;
    for (int ck = 0; ck < CHUNKS; ck++) {
        const bool more = (ck + 1 < CHUNKS);
        if (more) {
            const int kk = (ck + 1) * BKC;
#pragma unroll
            for (int p = 0; p < 4; p++)
                CP_ASYNC16(sbase + offA[buf ^ 1] + dstBase + p * 8192,
                           Ag + kk + (size_t)(p * 64) * H_);
#pragma unroll
            for (int p = 0; p < 2; p++)
                CP_ASYNC16(sbase + offB[buf ^ 1] + dstBase + p * 8192,
                           Bg + kk + (size_t)(p * 64) * H_);
            CP_COMMIT();
        }

        // ---- compute on buf ----
        const uint32_t aBuf = sbase + offA[buf];
        const uint32_t bBuf = sbase + offB[buf];
#pragma unroll
        for (int s = 0; s < 4; s++) {
            uint32_t afr[4][4];
#pragma unroll
            for (int mt = 0; mt < 4; mt++) {
                const int r = warpM * 64 + mt * 16 + (lane & 15);
                const int seg16 = 2 * s + (lane >> 4);
                ldsm4(afr[mt][0], afr[mt][1], afr[mt][2], afr[mt][3],
                      aBuf + r * 128 + ((seg16 ^ (r & 7)) << 4));
            }
#pragma unroll
            for (int q = 0; q < 2; q++) {
                uint32_t bq0, bq1, bq2, bq3;
                const int rn = warpN * 32 + q * 16 + ((lane >> 4) << 3) + (lane & 7);
                const int seg16 = 2 * s + ((lane >> 3) & 1);
                ldsm4(bq0, bq1, bq2, bq3,
                      bBuf + rn * 128 + ((seg16 ^ (rn & 7)) << 4));
#pragma unroll
                for (int mt = 0; mt < 4; mt++) {
                    mma_tf32(acc[mt][2 * q],     afr[mt], bq0, bq1);
                    mma_tf32(acc[mt][2 * q + 1], afr[mt], bq2, bq3);
                }
            }
        }

        if (more) CP_WAIT0();
        __syncthreads();
        buf ^= 1;
    }

    // ---- epilogue: sum_n tanh(D) * c over this CTA's 128 cols ----
#pragma unroll
    for (int mt = 0; mt < 4; mt++) {
        float slo = 0.f, shi = 0.f;
#pragma unroll
        for (int nt = 0; nt < 4; nt++) {
            const int n = warpN * 32 + nt * 8 + (lane & 3) * 2;
            const float c0 = cs[n], c1 = cs[n + 1];
            slo += tanhf(acc[mt][nt][0]) * c0 + tanhf(acc[mt][nt][1]) * c1;
            shi += tanhf(acc[mt][nt][2]) * c0 + tanhf(acc[mt][nt][3]) * c1;
        }
        slo += __shfl_xor_sync(0xffffffffu, slo, 1);
        slo += __shfl_xor_sync(0xffffffffu, slo, 2);
        shi += __shfl_xor_sync(0xffffffffu, shi, 1);
        shi += __shfl_xor_sync(0xffffffffu, shi, 2);
        if ((lane & 3) == 0) {
            const int r0 = warpM * 64 + mt * 16 + (lane >> 2);
            red[r0][warpN]     = slo;
            red[r0 + 8][warpN] = shi;
        }
    }
    __syncthreads();
    if (tid < BM)
        partials[(size_t)(rowBase + tid) * NCTILE + blockIdx.x] =
            (red[tid][0] + red[tid][1]) + (red[tid][2] + red[tid][3]);
}

// ---------------- kernel C: logits reduce + softmax over T ----------------
__global__ __launch_bounds__(1024) void softmax_kernel(
    const float* __restrict__ partials, float* __restrict__ out)
{
    __shared__ float lg[T_];
    __shared__ float redv[32];
    __shared__ float sBcast;
    const int b = blockIdx.x, tid = threadIdx.x;

    for (int t = tid; t < T_; t += 1024) {
        const float* p = &partials[(size_t)(b * T_ + t) * NCTILE];
        float s = 0.f;
#pragma unroll
        for (int q = 0; q < NCTILE; q++) s += p[q];
        lg[t] = s;
    }
    __syncthreads();

    float m = fmaxf(lg[tid], lg[tid + 1024]);
#pragma unroll
    for (int o = 16; o > 0; o >>= 1) m = fmaxf(m, __shfl_xor_sync(0xffffffffu, m, o));
    if ((tid & 31) == 0) redv[tid >> 5] = m;
    __syncthreads();
    if (tid < 32) {
        float v = redv[tid];
#pragma unroll
        for (int o = 16; o > 0; o >>= 1) v = fmaxf(v, __shfl_xor_sync(0xffffffffu, v, o));
        if (tid == 0) sBcast = v;
    }
    __syncthreads();
    const float M = sBcast;

    const float e0 = expf(lg[tid] - M);
    const float e1 = expf(lg[tid + 1024] - M);
    float z = e0 + e1;
#pragma unroll
    for (int o = 16; o > 0; o >>= 1) z += __shfl_xor_sync(0xffffffffu, z, o);
    if ((tid & 31) == 0) redv[tid >> 5] = z;
    __syncthreads();
    if (tid < 32) {
        float v = redv[tid];
#pragma unroll
        for (int o = 16; o > 0; o >>= 1) v += __shfl_xor_sync(0xffffffffu, v, o);
        if (tid == 0) sBcast = v;
    }
    __syncthreads();
    const float invZ = 1.0f / sBcast;

    float* attn = out + (size_t)B_ * H_ + (size_t)b * T_;
    attn[tid]        = e0 * invZ;
    attn[tid + 1024] = e1 * invZ;
}

// ---------------- kernel D1: context partials over 8 T-chunks ----------------
__global__ __launch_bounds__(256) void ctx_partial_kernel(
    const float* __restrict__ gru, const float* __restrict__ out,
    float* __restrict__ ctxp)
{
    __shared__ float at[CTS];
    const int hc = blockIdx.x, tc = blockIdx.y, b = blockIdx.z;
    const int h = hc * 256 + threadIdx.x;

    const float* attn = out + (size_t)B_ * H_ + (size_t)b * T_ + tc * CTS;
    if (threadIdx.x < CTS) at[threadIdx.x] = attn[threadIdx.x];
    __syncthreads();

    const float* g = gru + ((size_t)b * T_ + tc * CTS) * H_ + h;
    float acc = 0.f;
#pragma unroll 8
    for (int t = 0; t < CTS; t++) acc += at[t] * g[(size_t)t * H_];

    ctxp[((b * CTC + tc) * H_) + h] = acc;
}

// ---------------- kernel D2: reduce context partials ----------------
__global__ __launch_bounds__(256) void ctx_reduce_kernel(
    const float* __restrict__ ctxp, float* __restrict__ out)
{
    const int b = blockIdx.x;
    for (int h = threadIdx.x; h < H_; h += 256) {
        float s = 0.f;
#pragma unroll
        for (int q = 0; q < CTC; q++) s += ctxp[(b * CTC + q) * H_ + h];
        out[(size_t)b * H_ + h] = s;
    }
}

// ---------------- launch ----------------
extern "C" void kernel_launch(void* const* d_in, const int* in_sizes, int n_in,
                              void* d_out, int out_size) {
    const float* gru  = (const float*)d_in[0];
    const float* W    = (const float*)d_in[1];
    const float* cvec = (const float*)d_in[2];
    float* out = (float*)d_out;

    float *Wt = nullptr, *partials = nullptr, *ctxp = nullptr, *dmy = nullptr;
    cudaGetSymbolAddress((void**)&Wt, g_Wt);
    cudaGetSymbolAddress((void**)&partials, g_partials);
    cudaGetSymbolAddress((void**)&ctxp, g_ctxPartial);
    cudaGetSymbolAddress((void**)&dmy, g_dummy);

    cudaFuncSetAttribute(gemm_mma_kernel,
                         cudaFuncAttributeMaxDynamicSharedMemorySize, DSMEM_BYTES);

    transpose_w_kernel<<<dim3(32, 32), dim3(32, 8)>>>(W, Wt);      // idx 0
    dummy_kernel_a<<<1, 32>>>(dmy);                                 // idx 1
    dummy_kernel_b<<<1, 32>>>(dmy);                                 // idx 2

    gemm_mma_kernel<<<dim3(NCTILE, NROWS / BM), 512, DSMEM_BYTES>>>(gru, Wt, cvec, partials); // idx 3

    softmax_kernel<<<B_, 1024>>>(partials, out);

    ctx_partial_kernel<<<dim3(4, CTC, B_), 256>>>(gru, out, ctxp);

    ctx_reduce_kernel<<<B_, 256>>>(ctxp, out);
}